// round 10
// baseline (speedup 1.0000x reference)
#include <cuda_runtime.h>
#include <cuda_fp16.h>

// Morphological dilation2d, K=7, PAD=3 (zero padding = nn.Unfold), then ReLU.
// out[b,c,h,w] = max(0, max_{i,j}( xp[b,c,h+i,w+j] + weight[c,i,j] ))
// Packed fp16x2 (HADD2 + HMNMX2); ReLU folded into acc init (=0).
//
// This version removes per-tap PRMT from the compute loop by materializing a
// half-shifted copy of the slab in smem once per CTA, and fetches both weight
// rows per tap with a single broadcast LDS.64 from a paired weight table.
//
// x:      (16, 96, 128, 128) fp32 -> d_in[0]
// weight: (96, 7, 7)         fp32 -> d_in[1]
// out:    fp32

#define HH    128
#define WW    128
#define CC    96
#define BB    16
#define RPC   32            // output rows per CTA
#define SR    38            // smem rows = RPC + 6
#define SROWH 136           // smem row stride in HALVES (272B)
#define NT    256
#define NU4   ((SR * SROWH) / 8)   // 646 uint4 per slab

__device__ __forceinline__ __half2 u2h(unsigned u) { return *reinterpret_cast<__half2*>(&u); }

__global__ __launch_bounds__(NT, 6)
void morph7x7_h2_kernel(const float* __restrict__ x,
                        const float* __restrict__ wt,
                        float* __restrict__ out) {
    __shared__ __half xs [SR * SROWH + 8];   // original slab (+pad for shift overread)
    __shared__ __half xsh[SR * SROWH + 8];   // half-shifted slab: xsh[k] = xs[k+1]
    __shared__ uint2  wp[56];                // (w[s][j], w[s-1][j]) as half2-broadcast pair

    const int bid   = blockIdx.x;
    const int rtile = bid & 3;
    const int plane = bid >> 2;              // b*CC + c
    const int c     = plane % CC;
    const int R0    = rtile * RPC;

    const float* gx = x   + (size_t)plane * (HH * WW);
    float*       go = out + (size_t)plane * (HH * WW);
    const int tid = threadIdx.x;

    // ---- zero slab incl. pad (borders must be literal zeros) ----
    const uint4 z4 = {0u, 0u, 0u, 0u};
    #pragma unroll
    for (int i = tid; i < NU4 + 1; i += NT)
        reinterpret_cast<uint4*>(xs)[i] = z4;

    // ---- paired weight table: wp[s*7+j] = (w2[s][j], w2[s-1][j]) ----
    if (tid < 56) {
        const int s = tid / 7, j = tid % 7;
        unsigned w0 = 0u, w1 = 0u;
        if (s < 7) {
            __half2 h2 = __half2half2(__float2half_rn(wt[c * 49 + s * 7 + j]));
            w0 = *reinterpret_cast<unsigned*>(&h2);
        }
        if (s > 0) {
            __half2 h2 = __half2half2(__float2half_rn(wt[c * 49 + (s - 1) * 7 + j]));
            w1 = *reinterpret_cast<unsigned*>(&h2);
        }
        wp[tid] = make_uint2(w0, w1);
    }
    __syncthreads();

    // ---- load interior rows [g0,g1), fp32 -> fp16, data at half-col 4 ----
    const int g0 = (R0 - 3 > 0) ? R0 - 3 : 0;
    const int g1 = (R0 + 35 < HH) ? R0 + 35 : HH;
    const int n4 = (g1 - g0) * 32;           // float4 count
    #pragma unroll
    for (int idx = tid; idx < n4; idx += NT) {
        const int rr = idx >> 5;
        const int c4 = idx & 31;
        const int g  = g0 + rr;
        float4 v = reinterpret_cast<const float4*>(gx + g * WW)[c4];
        __half2 p0 = __floats2half2_rn(v.x, v.y);
        __half2 p1 = __floats2half2_rn(v.z, v.w);
        __half2* dst = reinterpret_cast<__half2*>(&xs[(g + 3 - R0) * SROWH + 4 + c4 * 4]);
        dst[0] = p0;
        dst[1] = p1;
    }
    __syncthreads();

    // ---- build half-shifted slab once: xsh2[k] = (xs[2k+1], xs[2k+2]) ----
    #pragma unroll
    for (int i = tid; i < NU4; i += NT) {
        const uint4 v  = reinterpret_cast<const uint4*>(xs)[i];
        const unsigned nxt = reinterpret_cast<const unsigned*>(xs)[i * 4 + 4];
        uint4 o;
        o.x = __byte_perm(v.x, v.y, 0x5432);
        o.y = __byte_perm(v.y, v.z, 0x5432);
        o.z = __byte_perm(v.z, v.w, 0x5432);
        o.w = __byte_perm(v.w, nxt, 0x5432);
        reinterpret_cast<uint4*>(xsh)[i] = o;
    }
    __syncthreads();

    // ---- compute: thread = 8 cols x 2 rows ----
    const int tx    = tid & 15;
    const int ty    = tid >> 4;
    const int cbase = tx * 8;                // output col base; all reads LDS.128-aligned
    const int r0    = ty * 2;

    const uint4* rb  = reinterpret_cast<const uint4*>(&xs [r0 * SROWH + cbase]);
    const uint4* rbs = reinterpret_cast<const uint4*>(&xsh[r0 * SROWH + cbase]);

    __half2 acc0[4], acc1[4];
    const __half2 h2z = __float2half2_rn(0.0f);
    #pragma unroll
    for (int p = 0; p < 4; ++p) { acc0[p] = h2z; acc1[p] = h2z; }   // folds ReLU

    #pragma unroll
    for (int s = 0; s < 8; ++s) {
        const uint4 A  = rb [s * 17];
        const uint4 B  = rb [s * 17 + 1];
        const uint4 As = rbs[s * 17];
        const uint4 Bs = rbs[s * 17 + 1];
        const unsigned h [8] = {A.x,  A.y,  A.z,  A.w,  B.x,  B.y,  B.z,  B.w};
        const unsigned hs[8] = {As.x, As.y, As.z, As.w, Bs.x, Bs.y, Bs.z, Bs.w};

        // tap j, output pair p: j even -> hs[j/2+p], j odd -> h[(j+1)/2+p]
        // acc0 uses weight row s (s<7); acc1 uses weight row s-1 (s>0).
        #pragma unroll
        for (int j = 0; j < 7; ++j) {
            const uint2 w = wp[s * 7 + j];       // one broadcast LDS.64
            const __half2 w0 = u2h(w.x);
            const __half2 w1 = u2h(w.y);
            #pragma unroll
            for (int p = 0; p < 4; ++p) {
                const __half2 tap = (j & 1) ? u2h(h[((j + 1) >> 1) + p])
                                            : u2h(hs[(j >> 1) + p]);
                if (s < 7) acc0[p] = __hmax2(acc0[p], __hadd2(tap, w0));
                if (s > 0) acc1[p] = __hmax2(acc1[p], __hadd2(tap, w1));
            }
        }
    }

    // ---- convert fp16 -> fp32, store 2x STG.128 per row ----
    {
        float2 f0 = __half22float2(acc0[0]);
        float2 f1 = __half22float2(acc0[1]);
        float2 f2 = __half22float2(acc0[2]);
        float2 f3 = __half22float2(acc0[3]);
        float4* op = reinterpret_cast<float4*>(&go[(R0 + r0) * WW + cbase]);
        op[0] = make_float4(f0.x, f0.y, f1.x, f1.y);
        op[1] = make_float4(f2.x, f2.y, f3.x, f3.y);
    }
    {
        float2 f0 = __half22float2(acc1[0]);
        float2 f1 = __half22float2(acc1[1]);
        float2 f2 = __half22float2(acc1[2]);
        float2 f3 = __half22float2(acc1[3]);
        float4* op = reinterpret_cast<float4*>(&go[(R0 + r0 + 1) * WW + cbase]);
        op[0] = make_float4(f0.x, f0.y, f1.x, f1.y);
        op[1] = make_float4(f2.x, f2.y, f3.x, f3.y);
    }
}

extern "C" void kernel_launch(void* const* d_in, const int* in_sizes, int n_in,
                              void* d_out, int out_size) {
    const float* x  = (const float*)d_in[0];
    const float* wt = (const float*)d_in[1];
    float* out = (float*)d_out;
    morph7x7_h2_kernel<<<BB * CC * 4, NT>>>(x, wt, out);
}

// round 11
// speedup vs baseline: 1.0819x; 1.0819x over previous
#include <cuda_runtime.h>
#include <cuda_fp16.h>

// Morphological dilation2d, K=7, PAD=3 (zero padding = nn.Unfold), then ReLU.
// out[b,c,h,w] = max(0, max_{i,j}( xp[b,c,h+i,w+j] + weight[c,i,j] ))
// Packed fp16x2 (HADD2 + HMNMX2); ReLU folded into acc init (=0).
// R9 structure (PRMT shift in registers, single slab) + paired weight table
// (one broadcast LDS.64 per tap fetches both weight rows) + 8 CTAs/SM.
//
// x:      (16, 96, 128, 128) fp32 -> d_in[0]
// weight: (96, 7, 7)         fp32 -> d_in[1]
// out:    fp32

#define HH    128
#define WW    128
#define CC    96
#define BB    16
#define RPC   32            // output rows per CTA
#define SR    38            // smem rows = RPC + 6
#define SROWH 136           // smem row stride in HALVES (272B)
#define NT    256

__device__ __forceinline__ __half2 u2h(unsigned u) { return *reinterpret_cast<__half2*>(&u); }

__global__ __launch_bounds__(NT, 8)
void morph7x7_h2_kernel(const float* __restrict__ x,
                        const float* __restrict__ wt,
                        float* __restrict__ out) {
    __shared__ __half xs[SR * SROWH];
    __shared__ uint2  wp[56];               // (w2[s][j], w2[s-1][j]) broadcast pairs

    const int bid   = blockIdx.x;
    const int rtile = bid & 3;
    const int plane = bid >> 2;             // b*CC + c
    const int c     = plane % CC;
    const int R0    = rtile * RPC;

    const float* gx = x   + (size_t)plane * (HH * WW);
    float*       go = out + (size_t)plane * (HH * WW);
    const int tid = threadIdx.x;

    // ---- zero slab (borders must be literal zeros) ----
    const uint4 z4 = {0u, 0u, 0u, 0u};
    #pragma unroll
    for (int i = tid; i < (SR * SROWH) / 8; i += NT)
        reinterpret_cast<uint4*>(xs)[i] = z4;

    // ---- paired weight table: wp[s*7+j] = (row s (s<7), row s-1 (s>0)) ----
    if (tid < 56) {
        const int s = tid / 7, j = tid % 7;
        unsigned w0 = 0u, w1 = 0u;
        if (s < 7) {
            __half2 h2 = __half2half2(__float2half_rn(wt[c * 49 + s * 7 + j]));
            w0 = *reinterpret_cast<unsigned*>(&h2);
        }
        if (s > 0) {
            __half2 h2 = __half2half2(__float2half_rn(wt[c * 49 + (s - 1) * 7 + j]));
            w1 = *reinterpret_cast<unsigned*>(&h2);
        }
        wp[tid] = make_uint2(w0, w1);
    }
    __syncthreads();

    // ---- load interior rows [g0,g1), fp32 -> fp16, data at half-col 4 ----
    const int g0 = (R0 - 3 > 0) ? R0 - 3 : 0;
    const int g1 = (R0 + 35 < HH) ? R0 + 35 : HH;
    const int n4 = (g1 - g0) * 32;          // float4 count
    #pragma unroll
    for (int idx = tid; idx < n4; idx += NT) {
        const int rr = idx >> 5;
        const int c4 = idx & 31;
        const int g  = g0 + rr;
        float4 v = reinterpret_cast<const float4*>(gx + g * WW)[c4];
        __half2 p0 = __floats2half2_rn(v.x, v.y);
        __half2 p1 = __floats2half2_rn(v.z, v.w);
        __half2* dst = reinterpret_cast<__half2*>(&xs[(g + 3 - R0) * SROWH + 4 + c4 * 4]);
        dst[0] = p0;
        dst[1] = p1;
    }
    __syncthreads();

    // ---- compute: thread = 8 cols x 2 rows ----
    const int tx    = tid & 15;
    const int ty    = tid >> 4;
    const int cbase = tx * 8;               // output col base; LDS.128-aligned reads
    const int r0    = ty * 2;

    // S[0..3]=0 pad; taps for output col w are S[w+1 .. w+7].
    const uint4* rb = reinterpret_cast<const uint4*>(&xs[r0 * SROWH + cbase]);

    __half2 acc0[4], acc1[4];
    const __half2 h2z = __float2half2_rn(0.0f);
    #pragma unroll
    for (int p = 0; p < 4; ++p) { acc0[p] = h2z; acc1[p] = h2z; }   // folds ReLU

    #pragma unroll
    for (int s = 0; s < 8; ++s) {
        const uint4 A = rb[s * 17];
        const uint4 B = rb[s * 17 + 1];
        const unsigned h[8] = {A.x, A.y, A.z, A.w, B.x, B.y, B.z, B.w};
        unsigned sft[7];
        #pragma unroll
        for (int m = 0; m < 7; ++m) sft[m] = __byte_perm(h[m], h[m + 1], 0x5432);

        // tap j, output pair p: j even -> sft[j/2+p], j odd -> h[(j+1)/2+p]
        // acc0 uses weight row s (s<7); acc1 uses weight row s-1 (s>0).
        #pragma unroll
        for (int j = 0; j < 7; ++j) {
            const uint2 w = wp[s * 7 + j];       // one broadcast LDS.64, both rows
            #pragma unroll
            for (int p = 0; p < 4; ++p) {
                const __half2 tap = (j & 1) ? u2h(h[((j + 1) >> 1) + p])
                                            : u2h(sft[(j >> 1) + p]);
                if (s < 7) acc0[p] = __hmax2(acc0[p], __hadd2(tap, u2h(w.x)));
                if (s > 0) acc1[p] = __hmax2(acc1[p], __hadd2(tap, u2h(w.y)));
            }
        }
    }

    // ---- convert fp16 -> fp32, store 2x STG.128 per row ----
    {
        float2 f0 = __half22float2(acc0[0]);
        float2 f1 = __half22float2(acc0[1]);
        float2 f2 = __half22float2(acc0[2]);
        float2 f3 = __half22float2(acc0[3]);
        float4* op = reinterpret_cast<float4*>(&go[(R0 + r0) * WW + cbase]);
        op[0] = make_float4(f0.x, f0.y, f1.x, f1.y);
        op[1] = make_float4(f2.x, f2.y, f3.x, f3.y);
    }
    {
        float2 f0 = __half22float2(acc1[0]);
        float2 f1 = __half22float2(acc1[1]);
        float2 f2 = __half22float2(acc1[2]);
        float2 f3 = __half22float2(acc1[3]);
        float4* op = reinterpret_cast<float4*>(&go[(R0 + r0 + 1) * WW + cbase]);
        op[0] = make_float4(f0.x, f0.y, f1.x, f1.y);
        op[1] = make_float4(f2.x, f2.y, f3.x, f3.y);
    }
}

extern "C" void kernel_launch(void* const* d_in, const int* in_sizes, int n_in,
                              void* d_out, int out_size) {
    const float* x  = (const float*)d_in[0];
    const float* wt = (const float*)d_in[1];
    float* out = (float*)d_out;
    morph7x7_h2_kernel<<<BB * CC * 4, NT>>>(x, wt, out);
}